// round 2
// baseline (speedup 1.0000x reference)
#include <cuda_runtime.h>
#include <cuda_bf16.h>

// Problem shape (fixed by the dataset)
#define Bv 8
#define Cv 256
#define Lv 4096
#define Kv 8

// Precomputed softmax time-weights: w[b][l][k], 8*4096*8 floats = 1 MB total.
// All 8 batches' w (8 MB) fit in L2 (~126 MB) and stay resident.
__device__ float g_w[Bv * Lv * Kv];

// ---------------------------------------------------------------------------
// Kernel 1: w[b,l,k] = softmax_k( dt[b,l-k] - dt[b,l] ), with the reference's
// BIG-sentinel semantics: for l < K-1 the masked taps dominate the softmax max
// so all *valid* weights are exactly 0 -> average_time == 0 there.
// ---------------------------------------------------------------------------
__global__ void __launch_bounds__(256) compute_w_kernel(const float* __restrict__ dt) {
    int idx = blockIdx.x * blockDim.x + threadIdx.x;   // idx = b*L + l
    if (idx >= Bv * Lv) return;
    int l = idx & (Lv - 1);
    float* wout = &g_w[(size_t)idx * Kv];

    if (l < Kv - 1) {
#pragma unroll
        for (int k = 0; k < Kv; k++) wout[k] = 0.0f;
        return;
    }

    float base = dt[idx];
    float d[Kv];
    float mx = -1e30f;
#pragma unroll
    for (int k = 0; k < Kv; k++) {
        d[k] = dt[idx - k] - base;
        mx = fmaxf(mx, d[k]);
    }
    float s = 0.0f;
#pragma unroll
    for (int k = 0; k < Kv; k++) {
        d[k] = __expf(d[k] - mx);
        s += d[k];
    }
    float inv = 1.0f / s;
#pragma unroll
    for (int k = 0; k < Kv; k++) wout[k] = d[k] * inv;
}

// ---------------------------------------------------------------------------
// Kernel 2: one CTA per PAIR of channels (same batch -> shared w row).
// 512 threads, each handles 8 contiguous elements of BOTH channel rows,
// fully register-resident (no smem for data; only a 6-scalar reduction).
//   Per thread:
//     - 4x LDG.128 per channel: x window [l0-8, l0+8)  (halo via overlap)
//     - 16x LDG.128 total for w (8 elements x 32B, shared by both channels)
//     - at/ap kept in registers; Gram partials reduced across the block
//     - 2x STG.128 per channel for the output
// ---------------------------------------------------------------------------
__global__ void __launch_bounds__(512) fused_kernel(
    const float* __restrict__ x,
    const float* __restrict__ kt,
    float* __restrict__ out)
{
    __shared__ float sred[16 * 6];   // 16 warps x {g00a,g01a,g11a,g00b,g01b,g11b}
    __shared__ float scoef[4];       // ca0, cb0, ca1, cb1

    const int r0 = blockIdx.x * 2;       // global row index (b*C + c), even
    const int r1 = r0 + 1;
    const int b  = r0 >> 8;              // Cv = 256
    const int tid = threadIdx.x;         // 0..511
    const int l0  = tid * 8;

    const float*  xr0 = x + (size_t)r0 * Lv;
    const float*  xr1 = x + (size_t)r1 * Lv;
    const float4* wr  = (const float4*)&g_w[(size_t)b * Lv * Kv];

    float ktr[Kv];
#pragma unroll
    for (int k = 0; k < Kv; k++) ktr[k] = __ldg(&kt[k]);

    // ---- load x windows [l0-8, l0+8) into registers (both channels) ----
    float xa[16], xb[16];
    {
        float4 va[4], vb[4];
        if (tid == 0) {
            va[0] = va[1] = make_float4(0.f, 0.f, 0.f, 0.f);
            vb[0] = vb[1] = va[0];
            const float4* p0 = (const float4*)xr0;
            const float4* p1 = (const float4*)xr1;
            va[2] = p0[0]; va[3] = p0[1];
            vb[2] = p1[0]; vb[3] = p1[1];
        } else {
            const float4* p0 = (const float4*)(xr0 + l0 - 8);
            const float4* p1 = (const float4*)(xr1 + l0 - 8);
#pragma unroll
            for (int j = 0; j < 4; j++) { va[j] = p0[j]; vb[j] = p1[j]; }
        }
#pragma unroll
        for (int j = 0; j < 4; j++) {
            xa[j*4+0] = va[j].x; xa[j*4+1] = va[j].y; xa[j*4+2] = va[j].z; xa[j*4+3] = va[j].w;
            xb[j*4+0] = vb[j].x; xb[j*4+1] = vb[j].y; xb[j*4+2] = vb[j].z; xb[j*4+3] = vb[j].w;
        }
    }

    // ---- main loop: at/ap for 8 elements of both channels ----
    float ata[8], apa[8], atb[8], apb[8];
    float g00a = 0.f, g01a = 0.f, g11a = 0.f;
    float g00b = 0.f, g01b = 0.f, g11b = 0.f;

#pragma unroll
    for (int i = 0; i < 8; i++) {
        float4 w0 = wr[(l0 + i) * 2];
        float4 w1 = wr[(l0 + i) * 2 + 1];
        float wv[Kv] = {w0.x, w0.y, w0.z, w0.w, w1.x, w1.y, w1.z, w1.w};

        float at0 = 0.f, ap0 = 0.f, at1 = 0.f, ap1 = 0.f;
#pragma unroll
        for (int k = 0; k < Kv; k++) {
            float va = xa[8 + i - k];
            float vb = xb[8 + i - k];
            at0 = fmaf(wv[k],  va, at0);
            ap0 = fmaf(ktr[k], va, ap0);
            at1 = fmaf(wv[k],  vb, at1);
            ap1 = fmaf(ktr[k], vb, ap1);
        }
        ata[i] = at0; apa[i] = ap0;
        atb[i] = at1; apb[i] = ap1;
        g00a = fmaf(at0, at0, g00a); g01a = fmaf(at0, ap0, g01a); g11a = fmaf(ap0, ap0, g11a);
        g00b = fmaf(at1, at1, g00b); g01b = fmaf(at1, ap1, g01b); g11b = fmaf(ap1, ap1, g11b);
    }

    // ---- block reduction of 6 Gram scalars ----
#pragma unroll
    for (int o = 16; o > 0; o >>= 1) {
        g00a += __shfl_xor_sync(0xffffffffu, g00a, o);
        g01a += __shfl_xor_sync(0xffffffffu, g01a, o);
        g11a += __shfl_xor_sync(0xffffffffu, g11a, o);
        g00b += __shfl_xor_sync(0xffffffffu, g00b, o);
        g01b += __shfl_xor_sync(0xffffffffu, g01b, o);
        g11b += __shfl_xor_sync(0xffffffffu, g11b, o);
    }
    int wid = tid >> 5, lid = tid & 31;
    if (lid == 0) {
        float* p = &sred[wid * 6];
        p[0] = g00a; p[1] = g01a; p[2] = g11a;
        p[3] = g00b; p[4] = g01b; p[5] = g11b;
    }
    __syncthreads();
    if (tid == 0) {
        float G[6] = {0.f, 0.f, 0.f, 0.f, 0.f, 0.f};
#pragma unroll
        for (int i = 0; i < 16; i++) {
#pragma unroll
            for (int j = 0; j < 6; j++) G[j] += sred[i * 6 + j];
        }
        // channel 0: scores row0 = softmax([G00,G01]); row1 = softmax([G01,G11])
        // out = 0.5*((s00+s10)*at + ((1-s00)+(1-s10))*ap)
        float s00 = 1.0f / (1.0f + __expf(G[1] - G[0]));
        float s10 = 1.0f / (1.0f + __expf(G[2] - G[1]));
        scoef[0] = 0.5f * (s00 + s10);
        scoef[1] = 0.5f * ((1.0f - s00) + (1.0f - s10));
        // channel 1
        float t00 = 1.0f / (1.0f + __expf(G[4] - G[3]));
        float t10 = 1.0f / (1.0f + __expf(G[5] - G[4]));
        scoef[2] = 0.5f * (t00 + t10);
        scoef[3] = 0.5f * ((1.0f - t00) + (1.0f - t10));
    }
    __syncthreads();

    // ---- output (register -> STG.128) ----
    const float ca0 = scoef[0], cb0 = scoef[1];
    const float ca1 = scoef[2], cb1 = scoef[3];
    float4* o0 = (float4*)(out + (size_t)r0 * Lv + l0);
    float4* o1 = (float4*)(out + (size_t)r1 * Lv + l0);
#pragma unroll
    for (int j = 0; j < 2; j++) {
        float4 va, vb;
        va.x = fmaf(ca0, ata[j*4+0], cb0 * apa[j*4+0]);
        va.y = fmaf(ca0, ata[j*4+1], cb0 * apa[j*4+1]);
        va.z = fmaf(ca0, ata[j*4+2], cb0 * apa[j*4+2]);
        va.w = fmaf(ca0, ata[j*4+3], cb0 * apa[j*4+3]);
        vb.x = fmaf(ca1, atb[j*4+0], cb1 * apb[j*4+0]);
        vb.y = fmaf(ca1, atb[j*4+1], cb1 * apb[j*4+1]);
        vb.z = fmaf(ca1, atb[j*4+2], cb1 * apb[j*4+2]);
        vb.w = fmaf(ca1, atb[j*4+3], cb1 * apb[j*4+3]);
        o0[j] = va;
        o1[j] = vb;
    }
}

// ---------------------------------------------------------------------------
extern "C" void kernel_launch(void* const* d_in, const int* in_sizes, int n_in,
                              void* d_out, int out_size) {
    const float* x  = (const float*)d_in[0];   // (B, C, L) f32
    const float* dt = (const float*)d_in[1];   // (B, L)    f32
    const float* kt = (const float*)d_in[2];   // (1, 1, K) f32
    float* out = (float*)d_out;                // (B, C, L) f32

    compute_w_kernel<<<(Bv * Lv + 255) / 256, 256>>>(dt);
    fused_kernel<<<Bv * Cv / 2, 512>>>(x, kt, out);
}

// round 3
// speedup vs baseline: 1.8389x; 1.8389x over previous
#include <cuda_runtime.h>
#include <cuda_bf16.h>

// Problem shape (fixed by the dataset)
#define Bv 8
#define Cv 256
#define Lv 4096
#define Kv 8
#define Gv 4            // channels per CTA (share one w row)
#define TPB 512
#define NJ (Lv / 4)     // float4s per row = 1024
#define ITERS (NJ / TPB)  // 2

// Transposed softmax time-weights: g_wt[k][b][l]. 8 planes of (B,L).
// Plane-major so per-tap loads are lane-contiguous (coalesced LDG.128).
__device__ float g_wt[Kv * Bv * Lv];

// ---------------------------------------------------------------------------
// Kernel 1: w[b,l,k] = softmax_k( dt[b,l-k] - dt[b,l] ), scattered to k-planes.
// BIG-sentinel semantics: for l < K-1 all valid weights are exactly 0.
// ---------------------------------------------------------------------------
__global__ void __launch_bounds__(256) compute_w_kernel(const float* __restrict__ dt) {
    int idx = blockIdx.x * blockDim.x + threadIdx.x;   // idx = b*L + l
    if (idx >= Bv * Lv) return;
    int l = idx & (Lv - 1);
    int b = idx >> 12;

    if (l < Kv - 1) {
#pragma unroll
        for (int k = 0; k < Kv; k++)
            g_wt[(k * Bv + b) * Lv + l] = 0.0f;
        return;
    }

    float base = dt[idx];
    float d[Kv];
    float mx = -1e30f;
#pragma unroll
    for (int k = 0; k < Kv; k++) {
        d[k] = dt[idx - k] - base;
        mx = fmaxf(mx, d[k]);
    }
    float s = 0.0f;
#pragma unroll
    for (int k = 0; k < Kv; k++) {
        d[k] = __expf(d[k] - mx);
        s += d[k];
    }
    float inv = 1.0f / s;
#pragma unroll
    for (int k = 0; k < Kv; k++)
        g_wt[(k * Bv + b) * Lv + l] = d[k] * inv;
}

// ---------------------------------------------------------------------------
// Kernel 2: one CTA per 4 channels of one batch. 512 threads.
// Lane-contiguous float4 mapping: thread handles float4 j = tid + i*512,
// i = 0..1, for each of the 4 channels.
//   - w loaded once per (i) into registers (8 x LDG.128, coalesced), reused
//     by all 4 channels.
//   - x halo (8 previous elements) via __shfl_up of the own float4; lanes 0/1
//     fix up from global (predicated, 2-lane LDG).
//   - at/ap stored in dynamic smem (128 KB) via STS.128, re-read in pass 2.
//   - Gram scalars reduced across the block -> 2x2 softmax -> coefficients.
// ---------------------------------------------------------------------------
#define SMEM_BYTES (2 * Gv * Lv * 4)   // sat + sap = 131072 bytes

__global__ void __launch_bounds__(TPB) fused_kernel(
    const float* __restrict__ x,
    const float* __restrict__ kt,
    float* __restrict__ out)
{
    extern __shared__ float smem[];
    float4* sat = (float4*)smem;               // [Gv][NJ]
    float4* sap = (float4*)(smem + Gv * Lv);   // [Gv][NJ]
    __shared__ float sred[16][12];
    __shared__ float scoef[2 * Gv];

    const int b   = blockIdx.x >> 6;           // / (Cv/Gv = 64)
    const int c0  = (blockIdx.x & 63) * Gv;
    const int tid = threadIdx.x;
    const int lid = tid & 31;
    const int wid = tid >> 5;

    float ktr[Kv];
#pragma unroll
    for (int k = 0; k < Kv; k++) ktr[k] = __ldg(&kt[k]);

    float gr[Gv][3];
#pragma unroll
    for (int g = 0; g < Gv; g++) { gr[g][0] = 0.f; gr[g][1] = 0.f; gr[g][2] = 0.f; }

#pragma unroll
    for (int i = 0; i < ITERS; i++) {
        const int j = tid + i * TPB;           // float4 index within row

        // w for elements 4j..4j+3, all 8 taps. Coalesced (plane-major).
        float4 wk[Kv];
#pragma unroll
        for (int k = 0; k < Kv; k++)
            wk[k] = ((const float4*)&g_wt[(size_t)(k * Bv + b) * Lv])[j];
        const float* wkf = (const float*)wk;   // wkf[k*4 + c]

#pragma unroll
        for (int g = 0; g < Gv; g++) {
            const float4* xr = (const float4*)(x + (size_t)(b * Cv + c0 + g) * Lv);
            float4 own = xr[j];

            // halo float4s j-1, j-2 via shuffle; lanes 0/1 fix up from global
            float4 hm1, hm2;
            hm1.x = __shfl_up_sync(0xffffffffu, own.x, 1);
            hm1.y = __shfl_up_sync(0xffffffffu, own.y, 1);
            hm1.z = __shfl_up_sync(0xffffffffu, own.z, 1);
            hm1.w = __shfl_up_sync(0xffffffffu, own.w, 1);
            hm2.x = __shfl_up_sync(0xffffffffu, own.x, 2);
            hm2.y = __shfl_up_sync(0xffffffffu, own.y, 2);
            hm2.z = __shfl_up_sync(0xffffffffu, own.z, 2);
            hm2.w = __shfl_up_sync(0xffffffffu, own.w, 2);
            if (lid == 0) {
                hm1 = (j >= 1) ? xr[j - 1] : make_float4(0.f, 0.f, 0.f, 0.f);
                hm2 = (j >= 2) ? xr[j - 2] : make_float4(0.f, 0.f, 0.f, 0.f);
            } else if (lid == 1) {
                hm2 = (j >= 2) ? xr[j - 2] : make_float4(0.f, 0.f, 0.f, 0.f);
            }

            // xw[m] = x[4j - 8 + m], m = 0..11
            float xw[12] = {hm2.x, hm2.y, hm2.z, hm2.w,
                            hm1.x, hm1.y, hm1.z, hm1.w,
                            own.x, own.y, own.z, own.w};

            float4 atv, apv;
            float* atf = (float*)&atv;
            float* apf = (float*)&apv;
#pragma unroll
            for (int c = 0; c < 4; c++) {
                float a_t = 0.f, a_p = 0.f;
#pragma unroll
                for (int k = 0; k < Kv; k++) {
                    float xv = xw[8 + c - k];
                    a_t = fmaf(wkf[k * 4 + c], xv, a_t);
                    a_p = fmaf(ktr[k],        xv, a_p);
                }
                atf[c] = a_t;
                apf[c] = a_p;
                gr[g][0] = fmaf(a_t, a_t, gr[g][0]);
                gr[g][1] = fmaf(a_t, a_p, gr[g][1]);
                gr[g][2] = fmaf(a_p, a_p, gr[g][2]);
            }
            sat[g * NJ + j] = atv;
            sap[g * NJ + j] = apv;
        }
    }

    // ---- block reduction of 12 Gram scalars ----
#pragma unroll
    for (int g = 0; g < Gv; g++) {
#pragma unroll
        for (int q = 0; q < 3; q++) {
            float v = gr[g][q];
#pragma unroll
            for (int o = 16; o > 0; o >>= 1)
                v += __shfl_xor_sync(0xffffffffu, v, o);
            gr[g][q] = v;
        }
    }
    if (lid == 0) {
#pragma unroll
        for (int g = 0; g < Gv; g++) {
            sred[wid][g * 3 + 0] = gr[g][0];
            sred[wid][g * 3 + 1] = gr[g][1];
            sred[wid][g * 3 + 2] = gr[g][2];
        }
    }
    __syncthreads();
    if (tid < Gv) {
        float G00 = 0.f, G01 = 0.f, G11 = 0.f;
#pragma unroll
        for (int wq = 0; wq < 16; wq++) {
            G00 += sred[wq][tid * 3 + 0];
            G01 += sred[wq][tid * 3 + 1];
            G11 += sred[wq][tid * 3 + 2];
        }
        // scores row0 = softmax([G00,G01]); row1 = softmax([G01,G11])
        // out = 0.5*((s00+s10)*at + ((1-s00)+(1-s10))*ap)
        float s00 = 1.0f / (1.0f + __expf(G01 - G00));
        float s10 = 1.0f / (1.0f + __expf(G11 - G01));
        scoef[2 * tid + 0] = 0.5f * (s00 + s10);
        scoef[2 * tid + 1] = 0.5f * ((1.0f - s00) + (1.0f - s10));
    }
    __syncthreads();

    // ---- pass 2: out = ca*at + cb*ap (coalesced STG.128) ----
#pragma unroll
    for (int g = 0; g < Gv; g++) {
        const float ca = scoef[2 * g + 0];
        const float cb = scoef[2 * g + 1];
        float4* orow = (float4*)(out + (size_t)(b * Cv + c0 + g) * Lv);
#pragma unroll
        for (int i = 0; i < ITERS; i++) {
            const int j = tid + i * TPB;
            float4 a = sat[g * NJ + j];
            float4 p = sap[g * NJ + j];
            float4 o;
            o.x = fmaf(ca, a.x, cb * p.x);
            o.y = fmaf(ca, a.y, cb * p.y);
            o.z = fmaf(ca, a.z, cb * p.z);
            o.w = fmaf(ca, a.w, cb * p.w);
            orow[j] = o;
        }
    }
}

// ---------------------------------------------------------------------------
extern "C" void kernel_launch(void* const* d_in, const int* in_sizes, int n_in,
                              void* d_out, int out_size) {
    const float* x  = (const float*)d_in[0];   // (B, C, L) f32
    const float* dt = (const float*)d_in[1];   // (B, L)    f32
    const float* kt = (const float*)d_in[2];   // (1, 1, K) f32
    float* out = (float*)d_out;                // (B, C, L) f32

    cudaFuncSetAttribute(fused_kernel,
                         cudaFuncAttributeMaxDynamicSharedMemorySize, SMEM_BYTES);

    compute_w_kernel<<<(Bv * Lv + 255) / 256, 256>>>(dt);
    fused_kernel<<<Bv * Cv / Gv, TPB, SMEM_BYTES>>>(x, kt, out);
}